// round 14
// baseline (speedup 1.0000x reference)
#include <cuda_runtime.h>
#include <cuda_bf16.h>
#include <math.h>
#include <stdint.h>

#define BB 16
#define SS 512
#define EE 256
#define HH 8
#define DD 32
#define TOK (BB*SS)
#define NEGBIG -1e30f

// ---------------- scratch ----------------
__device__ float g_in2E [TOK*2*EE];
__device__ float g_query[TOK*EE];
__device__ float g_x    [TOK*EE];
__device__ float g_cg   [TOK*EE];
__device__ float g_gg   [TOK*EE];
__device__ float g_q0   [TOK*EE];
__device__ float g_q1   [TOK*EE];
__device__ float g_k    [TOK*EE];
__device__ float g_v    [TOK*EE];
__device__ float g_out0 [TOK*EE];
__device__ float g_outF [TOK*EE];
__device__ float g_rel  [(size_t)BB*SS*SS];
__device__ float g_time [(size_t)BB*SS*SS];

// ---------------- fast exp on the FMA pipe ----------------
__device__ __forceinline__ float fexp(float x) {
    x = fmaxf(-80.0f, fminf(x, 80.0f));
    float y = x * 1.4426950408889634f;
    float t = y + 12582912.0f;               // rint via magic number
    int   e = __float_as_int(t) - 0x4B400000;
    float f = y - (t - 12582912.0f);         // [-0.5, 0.5]
    float p =            1.3333558146428443e-3f;
    p = fmaf(p, f, 9.6181298420717e-3f);
    p = fmaf(p, f, 5.550410866482158e-2f);
    p = fmaf(p, f, 2.402265069591007e-1f);
    p = fmaf(p, f, 6.931471805599453e-1f);
    p = fmaf(p, f, 1.0f);
    return p * __int_as_float((e + 127) << 23);
}

// ---------------- gather ----------------
__global__ void gather_kernel(const float* __restrict__ item_emb,
                              const int* __restrict__ item_inputs,
                              const int* __restrict__ label_inputs,
                              const int* __restrict__ item_ids)
{
    int tok = blockIdx.x;
    int t   = threadIdx.x;
    int idx = item_inputs[tok];
    int qid = item_ids[tok];
    float lab = (float)label_inputs[tok];
    float ie = item_emb[(size_t)idx*EE + t];
    g_in2E[(size_t)tok*2*EE + t]      = ie * lab;
    g_in2E[(size_t)tok*2*EE + EE + t] = ie * (1.0f - lab);
    g_query[(size_t)tok*EE + t] = item_emb[(size_t)qid*EE + t];
}

// ---------------- segmented bf16x3 tensor-core GEMM ----------------
struct GemmSegs {
    const float* W[4];
    const float* bias[4];
    float*       out[4];
    int          epi[4];
};

__device__ __forceinline__ uint32_t packbf(float v0, float v1) {
    __nv_bfloat16 a = __float2bfloat16_rn(v0);
    __nv_bfloat16 b = __float2bfloat16_rn(v1);
    return (uint32_t)__bfloat16_as_ushort(a) | ((uint32_t)__bfloat16_as_ushort(b) << 16);
}

#define MMA_BF16(d, a, b) \
    asm volatile("mma.sync.aligned.m16n8k16.row.col.f32.bf16.bf16.f32 " \
        "{%0,%1,%2,%3}, {%4,%5,%6,%7}, {%8,%9}, {%0,%1,%2,%3};\n" \
        : "+f"(d[0]), "+f"(d[1]), "+f"(d[2]), "+f"(d[3]) \
        : "r"(a.x), "r"(a.y), "r"(a.z), "r"(a.w), "r"(b.x), "r"(b.y))

__global__ __launch_bounds__(128)
void bf16gemm_seg(const float* __restrict__ A, int K, GemmSegs segs)
{
    __shared__ uint32_t As[2048];   // hi [0,1024), lo [1024,2048)
    __shared__ uint32_t Bs[2048];
    int t = threadIdx.x, lane = t & 31, wid = t >> 5;
    int wm = wid >> 1, wn = wid & 1;
    int m0 = blockIdx.y * 64, n0 = blockIdx.x * 64;
    int seg = n0 >> 8;
    const float* W    = segs.W[seg];
    const float* bias = segs.bias[seg];
    float*       Cout = segs.out[seg];
    int          epi  = segs.epi[seg];
    int ncol0 = n0 & 255;

    float acc[2][4][4];
    #pragma unroll
    for (int mi = 0; mi < 2; mi++)
        #pragma unroll
        for (int ni = 0; ni < 4; ni++)
            #pragma unroll
            for (int r = 0; r < 4; r++) acc[mi][ni][r] = 0.0f;

    for (int k0 = 0; k0 < K; k0 += 32) {
        __syncthreads();
        #pragma unroll
        for (int rep = 0; rep < 4; rep++) {
            int idx = t + rep*128;
            int row = idx >> 3;
            int kq  = (idx & 7) * 4;
            float4 av = *(const float4*)(A + (size_t)(m0+row)*K + k0 + kq);
            float v[4] = {av.x, av.y, av.z, av.w};
            int mt = row >> 4, mrow = row & 15;
            int g = mrow & 7, rh = mrow >> 3;
            #pragma unroll
            for (int pj = 0; pj < 2; pj++) {
                int k = kq + pj*2;
                int ks2 = k >> 4, kk = k & 15;
                int reg = rh + ((kk >> 3) << 1);
                int cq = (kk & 7) >> 1;
                float v0 = v[pj*2], v1 = v[pj*2+1];
                float h0 = __bfloat162float(__float2bfloat16_rn(v0));
                float h1 = __bfloat162float(__float2bfloat16_rn(v1));
                int addr = ((ks2*4 + mt)*32 + g*4 + cq)*4 + reg;
                As[addr]        = packbf(v0, v1);
                As[addr + 1024] = packbf(v0 - h0, v1 - h1);
            }
        }
        #pragma unroll
        for (int rep = 0; rep < 2; rep++) {
            int idx = t + rep*128;
            int kp = idx >> 4;
            int nq = (idx & 15) * 4;
            int k = kp*2;
            float4 b0 = *(const float4*)(W + (size_t)(k0+k  )*256 + ncol0 + nq);
            float4 b1 = *(const float4*)(W + (size_t)(k0+k+1)*256 + ncol0 + nq);
            float r0[4] = {b0.x, b0.y, b0.z, b0.w};
            float r1[4] = {b1.x, b1.y, b1.z, b1.w};
            int ks2 = k >> 4, kk = k & 15;
            int reg = kk >> 3, cq = (kk & 7) >> 1;
            #pragma unroll
            for (int j = 0; j < 4; j++) {
                int n = nq + j;
                int nt = n >> 3, g = n & 7;
                float h0 = __bfloat162float(__float2bfloat16_rn(r0[j]));
                float h1 = __bfloat162float(__float2bfloat16_rn(r1[j]));
                int addr = ((ks2*8 + nt)*32 + g*4 + cq)*2 + reg;
                Bs[addr]        = packbf(r0[j], r1[j]);
                Bs[addr + 1024] = packbf(r0[j] - h0, r1[j] - h1);
            }
        }
        __syncthreads();
        #pragma unroll
        for (int ks = 0; ks < 2; ks++) {
            uint4 ah[2], al[2];
            #pragma unroll
            for (int mi = 0; mi < 2; mi++) {
                ah[mi] = ((const uint4*)As)[(ks*4 + wm*2+mi)*32 + lane];
                al[mi] = ((const uint4*)As)[(ks*4 + wm*2+mi)*32 + lane + 256];
            }
            #pragma unroll
            for (int ni = 0; ni < 4; ni++) {
                uint2 bhp = ((const uint2*)Bs)[(ks*8 + wn*4+ni)*32 + lane];
                uint2 blp = ((const uint2*)Bs)[(ks*8 + wn*4+ni)*32 + lane + 512];
                #pragma unroll
                for (int mi = 0; mi < 2; mi++) {
                    MMA_BF16(acc[mi][ni], al[mi], bhp);
                    MMA_BF16(acc[mi][ni], ah[mi], blp);
                    MMA_BF16(acc[mi][ni], ah[mi], bhp);
                }
            }
        }
    }

    int g = lane >> 2, cq = lane & 3;
    #pragma unroll
    for (int mi = 0; mi < 2; mi++) {
        #pragma unroll
        for (int ni = 0; ni < 4; ni++) {
            #pragma unroll
            for (int r = 0; r < 4; r++) {
                int row = m0 + wm*32 + mi*16 + g + ((r >> 1) ? 8 : 0);
                int col = ncol0 + wn*32 + ni*8 + cq*2 + (r & 1);
                float v = acc[mi][ni][r];
                if (bias) v += bias[col];
                size_t oidx;
                if (epi == 0) {
                    int b = row >> 9, s = row & 511;
                    int h = col >> 5, d = col & 31;
                    oidx = (((size_t)(b*HH+h)*SS) + s)*DD + d;
                } else {
                    if (epi == 1) v = fmaxf(v, 0.0f);
                    else          v = 1.0f/(1.0f + fexp(-v));
                    oidx = (size_t)row*256 + col;
                }
                Cout[oidx] = v;
            }
        }
    }
}

// ---------------- row softmax: rel (mode0) / time (mode1) ----------------
__global__ void rowsm_kernel(const float* __restrict__ src, float* __restrict__ dst, int mode)
{
    int row = blockIdx.x;
    int i = row & (SS-1);
    int t = threadIdx.x;
    __shared__ float shs[8];
    const float2* sr = (const float2*)(src + (size_t)row*SS);
    float2 v = sr[t];
    int j0 = 2*t, j1 = 2*t + 1;
    float e0, e1;
    if (mode == 0) {
        e0 = (j0 <= i && v.x != 0.0f) ? fexp(v.x) : 0.0f;
        e1 = (j1 <= i && v.y != 0.0f) ? fexp(v.y) : 0.0f;
    } else {
        e0 = (j0 <= i) ? fexp(fexp(-fabsf(v.x))) : 0.0f;
        e1 = (j1 <= i) ? fexp(fexp(-fabsf(v.y))) : 0.0f;
    }
    int lane = t & 31, w = t >> 5;
    float s = e0 + e1;
    #pragma unroll
    for (int o = 16; o; o >>= 1) s += __shfl_xor_sync(0xffffffffu, s, o);
    if (lane == 0) shs[w] = s;
    __syncthreads();
    s = 0.0f;
    #pragma unroll
    for (int k = 0; k < 8; k++) s += shs[k];
    float inv = 1.0f / s;
    float2 o2 = make_float2(e0*inv, e1*inv);
    ((float2*)(dst + (size_t)row*SS))[t] = o2;
}

// ---------------- attention: 16 query rows / block (4 blocks/SM) ----------
#define AROWS 16
#define ATT_SMEM ((AROWS*512 + AROWS*32 + 2*2048 + AROWS*10 + AROWS*10)*4)
__global__ __launch_bounds__(256)
void attn_tile_kernel(const float* __restrict__ qh, const float* __restrict__ kh,
                      const float* __restrict__ vh,
                      const float* __restrict__ posK, const float* __restrict__ posV,
                      const float* __restrict__ l1p, const float* __restrict__ l2p,
                      float* __restrict__ out,
                      const float* __restrict__ out0_in,
                      float* __restrict__ attn_out,
                      int li)
{
    extern __shared__ float smf[];
    float* sc   = smf;                   // 16*512
    float* qs   = sc + AROWS*512;        // 16*32
    float* bufA = qs + AROWS*32;         // 2048
    float* bufB = bufA + 2048;           // 2048
    float* qpk  = bufB + 2048;           // 160
    float* pvw  = qpk + AROWS*10;        // 160

    int it = blockIdx.x;                 // 0..31
    int bh = blockIdx.y;
    int b = bh >> 3, h = bh & 7;
    int t = threadIdx.x;
    int i0 = it * AROWS;
    int ntile = it/4 + 1;
    int jact = ntile * 64;
    float l1 = l1p[0], l2 = l2p[0];
    float ca = (1.f-l1)*(1.f-l2), cb = l1*(1.f-l2), cc = l2;
    const float* qbase = qh + (size_t)bh*SS*DD;
    const float* kbase = kh + (size_t)bh*SS*DD;
    const float* vbase = vh + (size_t)bh*SS*DD;

    // q tile: 16*32 = 512 floats = 128 float4
    if (t < 128)
        ((float4*)qs)[t] = ((const float4*)(qbase + (size_t)i0*DD))[t];
    __syncthreads();
    if (t < 160) {
        int ii = t / 10, p = t % 10;
        float s = 0.f;
        #pragma unroll
        for (int d = 0; d < 32; d++) s += qs[ii*32+d] * posK[p*32+d];
        qpk[t] = s;
    }

    // ---- QK phase: 1 row x 4 cols per thread, double-buffered k tiles ----
    {
        #pragma unroll
        for (int rep = 0; rep < 2; rep++) {
            int idx = t + rep*256;
            int jj = idx >> 3, dq = (idx & 7) * 4;
            float4 kv = *(const float4*)(kbase + (size_t)jj*DD + dq);
            bufA[(dq+0)*64 + jj] = kv.x;
            bufA[(dq+1)*64 + jj] = kv.y;
            bufA[(dq+2)*64 + jj] = kv.z;
            bufA[(dq+3)*64 + jj] = kv.w;
        }
        __syncthreads();
        int rg = t >> 4, cg = t & 15;
        int i = i0 + rg;
        const float scale = 0.17677669529663687f;   // 1/sqrt(32)
        for (int jt = 0; jt < ntile; jt++) {
            float* cur = (jt & 1) ? bufB : bufA;
            float* nxt = (jt & 1) ? bufA : bufB;
            float4 pre[2];
            int jjp[2], dqp[2];
            if (jt+1 < ntile) {
                int j0n = (jt+1)*64;
                #pragma unroll
                for (int rep = 0; rep < 2; rep++) {
                    int idx = t + rep*256;
                    jjp[rep] = idx >> 3; dqp[rep] = (idx & 7) * 4;
                    pre[rep] = *(const float4*)(kbase + (size_t)(j0n+jjp[rep])*DD + dqp[rep]);
                }
            }
            float a0 = 0.f, a1 = 0.f, a2 = 0.f, a3 = 0.f;
            #pragma unroll
            for (int d = 0; d < 32; d += 4) {
                float4 q4 = *(const float4*)(qs + rg*32 + d);
                float qv[4] = {q4.x, q4.y, q4.z, q4.w};
                #pragma unroll
                for (int dd = 0; dd < 4; dd++) {
                    float4 bv = *(const float4*)(cur + (d+dd)*64 + cg*4);
                    a0 += qv[dd]*bv.x; a1 += qv[dd]*bv.y;
                    a2 += qv[dd]*bv.z; a3 += qv[dd]*bv.w;
                }
            }
            int j0 = jt*64;
            float acv[4] = {a0, a1, a2, a3};
            float o4[4];
            #pragma unroll
            for (int n = 0; n < 4; n++) {
                int j = j0 + cg*4 + n;
                o4[n] = (j <= i) ? (acv[n] + qpk[rg*10 + min(i-j, 9)]) * scale
                                 : NEGBIG;
            }
            *(float4*)(sc + rg*512 + j0 + cg*4) = make_float4(o4[0],o4[1],o4[2],o4[3]);
            if (jt+1 < ntile) {
                #pragma unroll
                for (int rep = 0; rep < 2; rep++) {
                    nxt[(dqp[rep]+0)*64 + jjp[rep]] = pre[rep].x;
                    nxt[(dqp[rep]+1)*64 + jjp[rep]] = pre[rep].y;
                    nxt[(dqp[rep]+2)*64 + jjp[rep]] = pre[rep].z;
                    nxt[(dqp[rep]+3)*64 + jjp[rep]] = pre[rep].w;
                }
            }
            __syncthreads();
        }
    }

    // ---- fused softmax + blend + buckets: warp w owns rows w*2..w*2+1 ----
    int w = t >> 5, lane = t & 31;
    int pairs = jact >> 1;
    for (int ii = w*2; ii < w*2 + 2; ii++) {
        int i = i0 + ii;
        float2* srow = (float2*)(sc + ii*512);
        float s = 0.f;
        for (int jp = lane; jp < pairs; jp += 32) {
            float2 e2 = srow[jp];
            e2.x = fexp(e2.x); e2.y = fexp(e2.y);
            srow[jp] = e2;
            s += e2.x + e2.y;
        }
        #pragma unroll
        for (int o = 16; o; o >>= 1) s += __shfl_xor_sync(0xffffffffu, s, o);
        float cap = ca / s;
        const float2* rel2 = (const float2*)(g_rel  + (size_t)(b*SS + i)*SS);
        const float2* tm2  = (const float2*)(g_time + (size_t)(b*SS + i)*SS);
        float unif = 1.0f / (float)(i + 1);
        float2* aout = attn_out ? (float2*)(attn_out + ((size_t)bh*SS + i)*SS) : nullptr;
        float s2 = 0.f;
        for (int jp = lane; jp < pairs; jp += 32) {
            float2 e2 = srow[jp];
            float2 r2 = rel2[jp];
            float tvx, tvy;
            if (li == 0) { float2 tt = tm2[jp]; tvx = tt.x; tvy = tt.y; }
            else {
                int j = jp*2;
                tvx = (j   <= i) ? unif : 0.0f;
                tvy = (j+1 <= i) ? unif : 0.0f;
            }
            float pfx = fmaf(cap, e2.x, fmaf(cb, r2.x, cc*tvx));
            float pfy = fmaf(cap, e2.y, fmaf(cb, r2.y, cc*tvy));
            float2 pf2 = make_float2(pfx, pfy);
            srow[jp] = pf2;
            if (aout) aout[jp] = pf2;
            s2 += pfx + pfy;
        }
        #pragma unroll
        for (int o = 16; o; o >>= 1) s2 += __shfl_xor_sync(0xffffffffu, s2, o);
        if (lane < 10) {
            int j = i - lane;
            pvw[ii*10 + lane] = (j >= 0) ? sc[ii*512 + j] : 0.0f;
        }
        __syncwarp();
        if (lane == 0) {
            float sum8 = 0.f;
            #pragma unroll
            for (int p = 0; p < 9; p++) sum8 += pvw[ii*10 + p];
            pvw[ii*10 + 9] = s2 - sum8;
        }
        __syncwarp();
    }
    if (attn_out) {
        int wtail = SS - jact;
        if (wtail > 0) {
            int cnt = (AROWS * wtail) >> 2;
            for (int f = t; f < cnt; f += 256) {
                int ii = (f*4) / wtail;
                int off = (f*4) % wtail;
                *(float4*)(attn_out + ((size_t)bh*SS + i0 + ii)*SS + jact + off) =
                    make_float4(0.f,0.f,0.f,0.f);
            }
        }
    }
    __syncthreads();

    // ---- PV phase: 1 row x 2 dims per thread, double-buffered v tiles ----
    {
        #pragma unroll
        for (int rep = 0; rep < 2; rep++)
            ((float4*)bufA)[t + rep*256] = ((const float4*)vbase)[t + rep*256];
        __syncthreads();
        int rg = t >> 4, cg = t & 15;
        float o0 = 0.f, o1 = 0.f;
        for (int jt = 0; jt < ntile; jt++) {
            float* cur = (jt & 1) ? bufB : bufA;
            float* nxt = (jt & 1) ? bufA : bufB;
            float4 pre[2];
            if (jt+1 < ntile) {
                #pragma unroll
                for (int rep = 0; rep < 2; rep++)
                    pre[rep] = ((const float4*)(vbase + (size_t)(jt+1)*64*DD))[t + rep*256];
            }
            const float* srow = sc + rg*512 + jt*64;
            #pragma unroll 8
            for (int jj = 0; jj < 64; jj++) {
                float p = srow[jj];
                float2 v2 = *(const float2*)(cur + jj*32 + cg*2);
                o0 += p*v2.x; o1 += p*v2.y;
            }
            if (jt+1 < ntile) {
                #pragma unroll
                for (int rep = 0; rep < 2; rep++)
                    ((float4*)nxt)[t + rep*256] = pre[rep];
            }
            __syncthreads();
        }
        #pragma unroll
        for (int p = 0; p < 10; p++) {
            float wv = pvw[rg*10 + p];
            float2 pv2 = *(const float2*)(posV + p*32 + cg*2);
            o0 += wv*pv2.x; o1 += wv*pv2.y;
        }
        int tok = b*SS + i0 + rg;
        int e0 = h*DD + cg*2;
        float2 gg2 = *(const float2*)(g_gg + (size_t)tok*EE + e0);
        float2 cg2 = *(const float2*)(g_cg + (size_t)tok*EE + e0);
        float2 val;
        val.x = gg2.x + (1.0f - cg2.x)*o0;
        val.y = gg2.y + (1.0f - cg2.y)*o1;
        if (li == 0) {
            *(float2*)(out + (size_t)tok*EE + e0) = val;
        } else {
            float2 b2 = *(const float2*)(out0_in + (size_t)tok*EE + e0);
            val.x = b2.x + fmaxf(val.x, 0.f);
            val.y = b2.y + fmaxf(val.y, 0.f);
            *(float2*)(out + (size_t)tok*EE + e0) = val;
        }
    }
}

// ---------------- final logits ----------------
__global__ void logits_kernel(const float* __restrict__ x, const float* __restrict__ wv,
                              const float* __restrict__ bv, float* __restrict__ out)
{
    int w = threadIdx.x >> 5, lane = threadIdx.x & 31;
    int tok = blockIdx.x*8 + w;
    float s = 0.f;
    for (int j = lane; j < EE; j += 32) s += x[(size_t)tok*EE + j] * wv[j];
    #pragma unroll
    for (int o = 16; o; o >>= 1) s += __shfl_xor_sync(0xffffffffu, s, o);
    if (lane == 0) out[tok] = s + bv[0];
}

extern "C" void kernel_launch(void* const* d_in, const int* in_sizes, int n_in,
                              void* d_out, int out_size)
{
    const int*   item_inputs  = (const int*)  d_in[2];
    const int*   label_inputs = (const int*)  d_in[3];
    const int*   item_ids     = (const int*)  d_in[4];
    const float* rel          = (const float*)d_in[5];
    const float* timestamp    = (const float*)d_in[6];
    const float* item_emb     = (const float*)d_in[7];
    const float* posK         = (const float*)d_in[8];
    const float* posV         = (const float*)d_in[9];
    const float* Wc           = (const float*)d_in[10];
    const float* Wg           = (const float*)d_in[11];
    const float* lin_in_w     = (const float*)d_in[12];
    const float* lin_in_b     = (const float*)d_in[13];
    const float* Wq           = (const float*)d_in[14];
    const float* bq           = (const float*)d_in[15];
    const float* Wk           = (const float*)d_in[16];
    const float* bk           = (const float*)d_in[17];
    const float* Wv           = (const float*)d_in[18];
    const float* bv           = (const float*)d_in[19];
    const float* l1           = (const float*)d_in[20];
    const float* l2           = (const float*)d_in[21];
    const float* lin_out_w    = (const float*)d_in[22];
    const float* lin_out_b    = (const float*)d_in[23];
    float* out = (float*)d_out;
    float* attn_out = out + TOK;   // [16,8,512,512] after [16,512,1]

    static int attr_done = 0;
    if (!attr_done) {
        cudaFuncSetAttribute(attn_tile_kernel,
                             cudaFuncAttributeMaxDynamicSharedMemorySize, ATT_SMEM);
        attr_done = 1;
    }

    float *p_in2E, *p_query, *p_x, *p_cg, *p_gg;
    float *p_q0, *p_q1, *p_k, *p_v, *p_out0, *p_outF, *p_rel, *p_time;
    cudaGetSymbolAddress((void**)&p_in2E,  g_in2E);
    cudaGetSymbolAddress((void**)&p_query, g_query);
    cudaGetSymbolAddress((void**)&p_x,     g_x);
    cudaGetSymbolAddress((void**)&p_cg,    g_cg);
    cudaGetSymbolAddress((void**)&p_gg,    g_gg);
    cudaGetSymbolAddress((void**)&p_q0,    g_q0);
    cudaGetSymbolAddress((void**)&p_q1,    g_q1);
    cudaGetSymbolAddress((void**)&p_k,     g_k);
    cudaGetSymbolAddress((void**)&p_v,     g_v);
    cudaGetSymbolAddress((void**)&p_out0,  g_out0);
    cudaGetSymbolAddress((void**)&p_outF,  g_outF);
    cudaGetSymbolAddress((void**)&p_rel,   g_rel);
    cudaGetSymbolAddress((void**)&p_time,  g_time);

    dim3 gatt(SS/AROWS, BB*HH);   // (32, 128) = 4096 blocks

    gather_kernel<<<TOK, EE>>>(item_emb, item_inputs, label_inputs, item_ids);

    // GEMM_A: x = relu(in2E @ lin_in_w + b)    [K=512, N=256]
    {
        GemmSegs s = {};
        s.W[0] = lin_in_w; s.bias[0] = lin_in_b; s.out[0] = p_x; s.epi[0] = 1;
        bf16gemm_seg<<<dim3(4, TOK/64), 128>>>(p_in2E, 2*EE, s);
    }
    // GEMM_B: query @ [Wc | Wg | Wq0 | Wq1]    [K=256, N=1024]
    {
        GemmSegs s = {};
        s.W[0] = Wc;        s.bias[0] = nullptr;  s.out[0] = p_cg; s.epi[0] = 2;
        s.W[1] = Wg;        s.bias[1] = nullptr;  s.out[1] = p_gg; s.epi[1] = 2;
        s.W[2] = Wq;        s.bias[2] = bq;       s.out[2] = p_q0; s.epi[2] = 0;
        s.W[3] = Wq+EE*EE;  s.bias[3] = bq+EE;    s.out[3] = p_q1; s.epi[3] = 0;
        bf16gemm_seg<<<dim3(16, TOK/64), 128>>>(p_query, EE, s);
    }
    rowsm_kernel<<<BB*SS, 256>>>(rel,       p_rel,  0);
    rowsm_kernel<<<BB*SS, 256>>>(timestamp, p_time, 1);

    // GEMM_C: x @ [Wk0 | Wv0]                  [K=256, N=512]
    {
        GemmSegs s = {};
        s.W[0] = Wk; s.bias[0] = bk; s.out[0] = p_k; s.epi[0] = 0;
        s.W[1] = Wv; s.bias[1] = bv; s.out[1] = p_v; s.epi[1] = 0;
        bf16gemm_seg<<<dim3(8, TOK/64), 128>>>(p_x, EE, s);
    }
    attn_tile_kernel<<<gatt, 256, ATT_SMEM>>>(p_q0, p_k, p_v, posK, posV, l1, l2,
                                              p_out0, nullptr, nullptr, 0);
    // GEMM_D: out0 @ [Wk1 | Wv1]               [K=256, N=512]
    {
        GemmSegs s = {};
        s.W[0] = Wk+EE*EE; s.bias[0] = bk+EE; s.out[0] = p_k; s.epi[0] = 0;
        s.W[1] = Wv+EE*EE; s.bias[1] = bv+EE; s.out[1] = p_v; s.epi[1] = 0;
        bf16gemm_seg<<<dim3(8, TOK/64), 128>>>(p_out0, EE, s);
    }
    attn_tile_kernel<<<gatt, 256, ATT_SMEM>>>(p_q1, p_k, p_v, posK, posV, l1, l2,
                                              p_outF, p_out0, attn_out, 1);

    logits_kernel<<<TOK/8, 256>>>(p_outF, lin_out_w, lin_out_b, out);
}

// round 15
// speedup vs baseline: 1.0042x; 1.0042x over previous
#include <cuda_runtime.h>
#include <cuda_bf16.h>
#include <math.h>
#include <stdint.h>

#define BB 16
#define SS 512
#define EE 256
#define HH 8
#define DD 32
#define TOK (BB*SS)
#define NEGBIG -1e30f

// ---------------- scratch ----------------
__device__ float g_in2E [TOK*2*EE];
__device__ float g_query[TOK*EE];
__device__ float g_x    [TOK*EE];
__device__ float g_cg   [TOK*EE];
__device__ float g_gg   [TOK*EE];
__device__ float g_q0   [TOK*EE];
__device__ float g_q1   [TOK*EE];
__device__ float g_k    [TOK*EE];
__device__ float g_v    [TOK*EE];
__device__ float g_out0 [TOK*EE];
__device__ float g_outF [TOK*EE];
__device__ float g_rel  [(size_t)BB*SS*SS];
__device__ float g_time [(size_t)BB*SS*SS];

// ---------------- fast exp on the FMA pipe ----------------
__device__ __forceinline__ float fexp(float x) {
    x = fmaxf(-80.0f, fminf(x, 80.0f));
    float y = x * 1.4426950408889634f;
    float t = y + 12582912.0f;               // rint via magic number
    int   e = __float_as_int(t) - 0x4B400000;
    float f = y - (t - 12582912.0f);         // [-0.5, 0.5]
    float p =            1.3333558146428443e-3f;
    p = fmaf(p, f, 9.6181298420717e-3f);
    p = fmaf(p, f, 5.550410866482158e-2f);
    p = fmaf(p, f, 2.402265069591007e-1f);
    p = fmaf(p, f, 6.931471805599453e-1f);
    p = fmaf(p, f, 1.0f);
    return p * __int_as_float((e + 127) << 23);
}

// ---------------- gather ----------------
__global__ void gather_kernel(const float* __restrict__ item_emb,
                              const int* __restrict__ item_inputs,
                              const int* __restrict__ label_inputs,
                              const int* __restrict__ item_ids)
{
    int tok = blockIdx.x;
    int t   = threadIdx.x;
    int idx = item_inputs[tok];
    int qid = item_ids[tok];
    float lab = (float)label_inputs[tok];
    float ie = item_emb[(size_t)idx*EE + t];
    g_in2E[(size_t)tok*2*EE + t]      = ie * lab;
    g_in2E[(size_t)tok*2*EE + EE + t] = ie * (1.0f - lab);
    g_query[(size_t)tok*EE + t] = item_emb[(size_t)qid*EE + t];
}

// ---------------- segmented bf16x3 tensor-core GEMM ----------------
struct GemmSegs {
    const float* W[4];
    const float* bias[4];
    float*       out[4];
    int          epi[4];
};

__device__ __forceinline__ uint32_t packbf(float v0, float v1) {
    __nv_bfloat16 a = __float2bfloat16_rn(v0);
    __nv_bfloat16 b = __float2bfloat16_rn(v1);
    return (uint32_t)__bfloat16_as_ushort(a) | ((uint32_t)__bfloat16_as_ushort(b) << 16);
}

#define MMA_BF16(d, a, b) \
    asm volatile("mma.sync.aligned.m16n8k16.row.col.f32.bf16.bf16.f32 " \
        "{%0,%1,%2,%3}, {%4,%5,%6,%7}, {%8,%9}, {%0,%1,%2,%3};\n" \
        : "+f"(d[0]), "+f"(d[1]), "+f"(d[2]), "+f"(d[3]) \
        : "r"(a.x), "r"(a.y), "r"(a.z), "r"(a.w), "r"(b.x), "r"(b.y))

__global__ __launch_bounds__(128)
void bf16gemm_seg(const float* __restrict__ A, int K, GemmSegs segs)
{
    __shared__ uint32_t As[2048];   // hi [0,1024), lo [1024,2048)
    __shared__ uint32_t Bs[2048];
    int t = threadIdx.x, lane = t & 31, wid = t >> 5;
    int wm = wid >> 1, wn = wid & 1;
    int m0 = blockIdx.y * 64, n0 = blockIdx.x * 64;
    int seg = n0 >> 8;
    const float* W    = segs.W[seg];
    const float* bias = segs.bias[seg];
    float*       Cout = segs.out[seg];
    int          epi  = segs.epi[seg];
    int ncol0 = n0 & 255;

    float acc[2][4][4];
    #pragma unroll
    for (int mi = 0; mi < 2; mi++)
        #pragma unroll
        for (int ni = 0; ni < 4; ni++)
            #pragma unroll
            for (int r = 0; r < 4; r++) acc[mi][ni][r] = 0.0f;

    for (int k0 = 0; k0 < K; k0 += 32) {
        __syncthreads();
        #pragma unroll
        for (int rep = 0; rep < 4; rep++) {
            int idx = t + rep*128;
            int row = idx >> 3;
            int kq  = (idx & 7) * 4;
            float4 av = *(const float4*)(A + (size_t)(m0+row)*K + k0 + kq);
            float v[4] = {av.x, av.y, av.z, av.w};
            int mt = row >> 4, mrow = row & 15;
            int g = mrow & 7, rh = mrow >> 3;
            #pragma unroll
            for (int pj = 0; pj < 2; pj++) {
                int k = kq + pj*2;
                int ks2 = k >> 4, kk = k & 15;
                int reg = rh + ((kk >> 3) << 1);
                int cq = (kk & 7) >> 1;
                float v0 = v[pj*2], v1 = v[pj*2+1];
                float h0 = __bfloat162float(__float2bfloat16_rn(v0));
                float h1 = __bfloat162float(__float2bfloat16_rn(v1));
                int addr = ((ks2*4 + mt)*32 + g*4 + cq)*4 + reg;
                As[addr]        = packbf(v0, v1);
                As[addr + 1024] = packbf(v0 - h0, v1 - h1);
            }
        }
        #pragma unroll
        for (int rep = 0; rep < 2; rep++) {
            int idx = t + rep*128;
            int kp = idx >> 4;
            int nq = (idx & 15) * 4;
            int k = kp*2;
            float4 b0 = *(const float4*)(W + (size_t)(k0+k  )*256 + ncol0 + nq);
            float4 b1 = *(const float4*)(W + (size_t)(k0+k+1)*256 + ncol0 + nq);
            float r0[4] = {b0.x, b0.y, b0.z, b0.w};
            float r1[4] = {b1.x, b1.y, b1.z, b1.w};
            int ks2 = k >> 4, kk = k & 15;
            int reg = kk >> 3, cq = (kk & 7) >> 1;
            #pragma unroll
            for (int j = 0; j < 4; j++) {
                int n = nq + j;
                int nt = n >> 3, g = n & 7;
                float h0 = __bfloat162float(__float2bfloat16_rn(r0[j]));
                float h1 = __bfloat162float(__float2bfloat16_rn(r1[j]));
                int addr = ((ks2*8 + nt)*32 + g*4 + cq)*2 + reg;
                Bs[addr]        = packbf(r0[j], r1[j]);
                Bs[addr + 1024] = packbf(r0[j] - h0, r1[j] - h1);
            }
        }
        __syncthreads();
        #pragma unroll
        for (int ks = 0; ks < 2; ks++) {
            uint4 ah[2], al[2];
            #pragma unroll
            for (int mi = 0; mi < 2; mi++) {
                ah[mi] = ((const uint4*)As)[(ks*4 + wm*2+mi)*32 + lane];
                al[mi] = ((const uint4*)As)[(ks*4 + wm*2+mi)*32 + lane + 256];
            }
            #pragma unroll
            for (int ni = 0; ni < 4; ni++) {
                uint2 bhp = ((const uint2*)Bs)[(ks*8 + wn*4+ni)*32 + lane];
                uint2 blp = ((const uint2*)Bs)[(ks*8 + wn*4+ni)*32 + lane + 512];
                #pragma unroll
                for (int mi = 0; mi < 2; mi++) {
                    MMA_BF16(acc[mi][ni], al[mi], bhp);
                    MMA_BF16(acc[mi][ni], ah[mi], blp);
                    MMA_BF16(acc[mi][ni], ah[mi], bhp);
                }
            }
        }
    }

    int g = lane >> 2, cq = lane & 3;
    #pragma unroll
    for (int mi = 0; mi < 2; mi++) {
        #pragma unroll
        for (int ni = 0; ni < 4; ni++) {
            #pragma unroll
            for (int r = 0; r < 4; r++) {
                int row = m0 + wm*32 + mi*16 + g + ((r >> 1) ? 8 : 0);
                int col = ncol0 + wn*32 + ni*8 + cq*2 + (r & 1);
                float v = acc[mi][ni][r];
                if (bias) v += bias[col];
                size_t oidx;
                if (epi == 0) {
                    int b = row >> 9, s = row & 511;
                    int h = col >> 5, d = col & 31;
                    oidx = (((size_t)(b*HH+h)*SS) + s)*DD + d;
                } else {
                    if (epi == 1) v = fmaxf(v, 0.0f);
                    else          v = 1.0f/(1.0f + fexp(-v));
                    oidx = (size_t)row*256 + col;
                }
                Cout[oidx] = v;
            }
        }
    }
}

// ---------------- row softmax: rel (mode0) / time (mode1) ----------------
__global__ void rowsm_kernel(const float* __restrict__ src, float* __restrict__ dst, int mode)
{
    int row = blockIdx.x;
    int i = row & (SS-1);
    int t = threadIdx.x;
    __shared__ float shs[8];
    const float2* sr = (const float2*)(src + (size_t)row*SS);
    float2 v = sr[t];
    int j0 = 2*t, j1 = 2*t + 1;
    float e0, e1;
    if (mode == 0) {
        e0 = (j0 <= i && v.x != 0.0f) ? fexp(v.x) : 0.0f;
        e1 = (j1 <= i && v.y != 0.0f) ? fexp(v.y) : 0.0f;
    } else {
        e0 = (j0 <= i) ? fexp(fexp(-fabsf(v.x))) : 0.0f;
        e1 = (j1 <= i) ? fexp(fexp(-fabsf(v.y))) : 0.0f;
    }
    int lane = t & 31, w = t >> 5;
    float s = e0 + e1;
    #pragma unroll
    for (int o = 16; o; o >>= 1) s += __shfl_xor_sync(0xffffffffu, s, o);
    if (lane == 0) shs[w] = s;
    __syncthreads();
    s = 0.0f;
    #pragma unroll
    for (int k = 0; k < 8; k++) s += shs[k];
    float inv = 1.0f / s;
    float2 o2 = make_float2(e0*inv, e1*inv);
    ((float2*)(dst + (size_t)row*SS))[t] = o2;
}

// ---------------- attention: 16 query rows / block (4 blocks/SM) ----------
#define AROWS 16
#define ATT_SMEM ((AROWS*512 + AROWS*32 + 2*2048 + AROWS*10 + AROWS*10)*4)
__global__ __launch_bounds__(256)
void attn_tile_kernel(const float* __restrict__ qh, const float* __restrict__ kh,
                      const float* __restrict__ vh,
                      const float* __restrict__ posK, const float* __restrict__ posV,
                      const float* __restrict__ l1p, const float* __restrict__ l2p,
                      float* __restrict__ out,
                      const float* __restrict__ out0_in,
                      float* __restrict__ attn_out,
                      int li)
{
    extern __shared__ float smf[];
    float* sc   = smf;                   // 16*512
    float* qs   = sc + AROWS*512;        // 16*32
    float* bufA = qs + AROWS*32;         // 2048
    float* bufB = bufA + 2048;           // 2048
    float* qpk  = bufB + 2048;           // 160
    float* pvw  = qpk + AROWS*10;        // 160

    int it = blockIdx.x;                 // 0..31
    int bh = blockIdx.y;
    int b = bh >> 3, h = bh & 7;
    int t = threadIdx.x;
    int i0 = it * AROWS;
    int ntile = it/4 + 1;
    int jact = ntile * 64;
    float l1 = l1p[0], l2 = l2p[0];
    float ca = (1.f-l1)*(1.f-l2), cb = l1*(1.f-l2), cc = l2;
    const float* qbase = qh + (size_t)bh*SS*DD;
    const float* kbase = kh + (size_t)bh*SS*DD;
    const float* vbase = vh + (size_t)bh*SS*DD;

    // q tile: 16*32 = 512 floats = 128 float4
    if (t < 128)
        ((float4*)qs)[t] = ((const float4*)(qbase + (size_t)i0*DD))[t];
    __syncthreads();
    if (t < 160) {
        int ii = t / 10, p = t % 10;
        float s = 0.f;
        #pragma unroll
        for (int d = 0; d < 32; d++) s += qs[ii*32+d] * posK[p*32+d];
        qpk[t] = s;
    }

    // ---- QK phase: 1 row x 4 cols per thread, double-buffered k tiles ----
    {
        #pragma unroll
        for (int rep = 0; rep < 2; rep++) {
            int idx = t + rep*256;
            int jj = idx >> 3, dq = (idx & 7) * 4;
            float4 kv = *(const float4*)(kbase + (size_t)jj*DD + dq);
            bufA[(dq+0)*64 + jj] = kv.x;
            bufA[(dq+1)*64 + jj] = kv.y;
            bufA[(dq+2)*64 + jj] = kv.z;
            bufA[(dq+3)*64 + jj] = kv.w;
        }
        __syncthreads();
        int rg = t >> 4, cg = t & 15;
        int i = i0 + rg;
        const float scale = 0.17677669529663687f;   // 1/sqrt(32)
        for (int jt = 0; jt < ntile; jt++) {
            float* cur = (jt & 1) ? bufB : bufA;
            float* nxt = (jt & 1) ? bufA : bufB;
            float4 pre[2];
            int jjp[2], dqp[2];
            if (jt+1 < ntile) {
                int j0n = (jt+1)*64;
                #pragma unroll
                for (int rep = 0; rep < 2; rep++) {
                    int idx = t + rep*256;
                    jjp[rep] = idx >> 3; dqp[rep] = (idx & 7) * 4;
                    pre[rep] = *(const float4*)(kbase + (size_t)(j0n+jjp[rep])*DD + dqp[rep]);
                }
            }
            float a0 = 0.f, a1 = 0.f, a2 = 0.f, a3 = 0.f;
            #pragma unroll
            for (int d = 0; d < 32; d += 4) {
                float4 q4 = *(const float4*)(qs + rg*32 + d);
                float qv[4] = {q4.x, q4.y, q4.z, q4.w};
                #pragma unroll
                for (int dd = 0; dd < 4; dd++) {
                    float4 bv = *(const float4*)(cur + (d+dd)*64 + cg*4);
                    a0 += qv[dd]*bv.x; a1 += qv[dd]*bv.y;
                    a2 += qv[dd]*bv.z; a3 += qv[dd]*bv.w;
                }
            }
            int j0 = jt*64;
            float acv[4] = {a0, a1, a2, a3};
            float o4[4];
            #pragma unroll
            for (int n = 0; n < 4; n++) {
                int j = j0 + cg*4 + n;
                o4[n] = (j <= i) ? (acv[n] + qpk[rg*10 + min(i-j, 9)]) * scale
                                 : NEGBIG;
            }
            *(float4*)(sc + rg*512 + j0 + cg*4) = make_float4(o4[0],o4[1],o4[2],o4[3]);
            if (jt+1 < ntile) {
                #pragma unroll
                for (int rep = 0; rep < 2; rep++) {
                    nxt[(dqp[rep]+0)*64 + jjp[rep]] = pre[rep].x;
                    nxt[(dqp[rep]+1)*64 + jjp[rep]] = pre[rep].y;
                    nxt[(dqp[rep]+2)*64 + jjp[rep]] = pre[rep].z;
                    nxt[(dqp[rep]+3)*64 + jjp[rep]] = pre[rep].w;
                }
            }
            __syncthreads();
        }
    }

    // ---- fused softmax + blend + buckets: warp w owns rows w*2..w*2+1 ----
    int w = t >> 5, lane = t & 31;
    int pairs = jact >> 1;
    for (int ii = w*2; ii < w*2 + 2; ii++) {
        int i = i0 + ii;
        float2* srow = (float2*)(sc + ii*512);
        float s = 0.f;
        for (int jp = lane; jp < pairs; jp += 32) {
            float2 e2 = srow[jp];
            e2.x = fexp(e2.x); e2.y = fexp(e2.y);
            srow[jp] = e2;
            s += e2.x + e2.y;
        }
        #pragma unroll
        for (int o = 16; o; o >>= 1) s += __shfl_xor_sync(0xffffffffu, s, o);
        float cap = ca / s;
        const float2* rel2 = (const float2*)(g_rel  + (size_t)(b*SS + i)*SS);
        const float2* tm2  = (const float2*)(g_time + (size_t)(b*SS + i)*SS);
        float unif = 1.0f / (float)(i + 1);
        float2* aout = attn_out ? (float2*)(attn_out + ((size_t)bh*SS + i)*SS) : nullptr;
        float s2 = 0.f;
        for (int jp = lane; jp < pairs; jp += 32) {
            float2 e2 = srow[jp];
            float2 r2 = rel2[jp];
            float tvx, tvy;
            if (li == 0) { float2 tt = tm2[jp]; tvx = tt.x; tvy = tt.y; }
            else {
                int j = jp*2;
                tvx = (j   <= i) ? unif : 0.0f;
                tvy = (j+1 <= i) ? unif : 0.0f;
            }
            float pfx = fmaf(cap, e2.x, fmaf(cb, r2.x, cc*tvx));
            float pfy = fmaf(cap, e2.y, fmaf(cb, r2.y, cc*tvy));
            float2 pf2 = make_float2(pfx, pfy);
            srow[jp] = pf2;
            if (aout) aout[jp] = pf2;
            s2 += pfx + pfy;
        }
        #pragma unroll
        for (int o = 16; o; o >>= 1) s2 += __shfl_xor_sync(0xffffffffu, s2, o);
        if (lane < 10) {
            int j = i - lane;
            pvw[ii*10 + lane] = (j >= 0) ? sc[ii*512 + j] : 0.0f;
        }
        __syncwarp();
        if (lane == 0) {
            float sum8 = 0.f;
            #pragma unroll
            for (int p = 0; p < 9; p++) sum8 += pvw[ii*10 + p];
            pvw[ii*10 + 9] = s2 - sum8;
        }
        __syncwarp();
    }
    if (attn_out) {
        int wtail = SS - jact;
        if (wtail > 0) {
            int cnt = (AROWS * wtail) >> 2;
            for (int f = t; f < cnt; f += 256) {
                int ii = (f*4) / wtail;
                int off = (f*4) % wtail;
                *(float4*)(attn_out + ((size_t)bh*SS + i0 + ii)*SS + jact + off) =
                    make_float4(0.f,0.f,0.f,0.f);
            }
        }
    }
    __syncthreads();

    // ---- PV phase: 1 row x 2 dims per thread, double-buffered v tiles ----
    {
        #pragma unroll
        for (int rep = 0; rep < 2; rep++)
            ((float4*)bufA)[t + rep*256] = ((const float4*)vbase)[t + rep*256];
        __syncthreads();
        int rg = t >> 4, cg = t & 15;
        float o0 = 0.f, o1 = 0.f;
        for (int jt = 0; jt < ntile; jt++) {
            float* cur = (jt & 1) ? bufB : bufA;
            float* nxt = (jt & 1) ? bufA : bufB;
            float4 pre[2];
            if (jt+1 < ntile) {
                #pragma unroll
                for (int rep = 0; rep < 2; rep++)
                    pre[rep] = ((const float4*)(vbase + (size_t)(jt+1)*64*DD))[t + rep*256];
            }
            const float* srow = sc + rg*512 + jt*64;
            #pragma unroll 8
            for (int jj = 0; jj < 64; jj++) {
                float p = srow[jj];
                float2 v2 = *(const float2*)(cur + jj*32 + cg*2);
                o0 += p*v2.x; o1 += p*v2.y;
            }
            if (jt+1 < ntile) {
                #pragma unroll
                for (int rep = 0; rep < 2; rep++)
                    ((float4*)nxt)[t + rep*256] = pre[rep];
            }
            __syncthreads();
        }
        #pragma unroll
        for (int p = 0; p < 10; p++) {
            float wv = pvw[rg*10 + p];
            float2 pv2 = *(const float2*)(posV + p*32 + cg*2);
            o0 += wv*pv2.x; o1 += wv*pv2.y;
        }
        int tok = b*SS + i0 + rg;
        int e0 = h*DD + cg*2;
        float2 gg2 = *(const float2*)(g_gg + (size_t)tok*EE + e0);
        float2 cg2 = *(const float2*)(g_cg + (size_t)tok*EE + e0);
        float2 val;
        val.x = gg2.x + (1.0f - cg2.x)*o0;
        val.y = gg2.y + (1.0f - cg2.y)*o1;
        if (li == 0) {
            *(float2*)(out + (size_t)tok*EE + e0) = val;
        } else {
            float2 b2 = *(const float2*)(out0_in + (size_t)tok*EE + e0);
            val.x = b2.x + fmaxf(val.x, 0.f);
            val.y = b2.y + fmaxf(val.y, 0.f);
            *(float2*)(out + (size_t)tok*EE + e0) = val;
        }
    }
}

// ---------------- final logits ----------------
__global__ void logits_kernel(const float* __restrict__ x, const float* __restrict__ wv,
                              const float* __restrict__ bv, float* __restrict__ out)
{
    int w = threadIdx.x >> 5, lane = threadIdx.x & 31;
    int tok = blockIdx.x*8 + w;
    float s = 0.f;
    for (int j = lane; j < EE; j += 32) s += x[(size_t)tok*EE + j] * wv[j];
    #pragma unroll
    for (int o = 16; o; o >>= 1) s += __shfl_xor_sync(0xffffffffu, s, o);
    if (lane == 0) out[tok] = s + bv[0];
}

extern "C" void kernel_launch(void* const* d_in, const int* in_sizes, int n_in,
                              void* d_out, int out_size)
{
    const int*   item_inputs  = (const int*)  d_in[2];
    const int*   label_inputs = (const int*)  d_in[3];
    const int*   item_ids     = (const int*)  d_in[4];
    const float* rel          = (const float*)d_in[5];
    const float* timestamp    = (const float*)d_in[6];
    const float* item_emb     = (const float*)d_in[7];
    const float* posK         = (const float*)d_in[8];
    const float* posV         = (const float*)d_in[9];
    const float* Wc           = (const float*)d_in[10];
    const float* Wg           = (const float*)d_in[11];
    const float* lin_in_w     = (const float*)d_in[12];
    const float* lin_in_b     = (const float*)d_in[13];
    const float* Wq           = (const float*)d_in[14];
    const float* bq           = (const float*)d_in[15];
    const float* Wk           = (const float*)d_in[16];
    const float* bk           = (const float*)d_in[17];
    const float* Wv           = (const float*)d_in[18];
    const float* bv           = (const float*)d_in[19];
    const float* l1           = (const float*)d_in[20];
    const float* l2           = (const float*)d_in[21];
    const float* lin_out_w    = (const float*)d_in[22];
    const float* lin_out_b    = (const float*)d_in[23];
    float* out = (float*)d_out;
    float* attn_out = out + TOK;   // [16,8,512,512] after [16,512,1]

    static int attr_done = 0;
    if (!attr_done) {
        cudaFuncSetAttribute(attn_tile_kernel,
                             cudaFuncAttributeMaxDynamicSharedMemorySize, ATT_SMEM);
        attr_done = 1;
    }

    float *p_in2E, *p_query, *p_x, *p_cg, *p_gg;
    float *p_q0, *p_q1, *p_k, *p_v, *p_out0, *p_outF, *p_rel, *p_time;
    cudaGetSymbolAddress((void**)&p_in2E,  g_in2E);
    cudaGetSymbolAddress((void**)&p_query, g_query);
    cudaGetSymbolAddress((void**)&p_x,     g_x);
    cudaGetSymbolAddress((void**)&p_cg,    g_cg);
    cudaGetSymbolAddress((void**)&p_gg,    g_gg);
    cudaGetSymbolAddress((void**)&p_q0,    g_q0);
    cudaGetSymbolAddress((void**)&p_q1,    g_q1);
    cudaGetSymbolAddress((void**)&p_k,     g_k);
    cudaGetSymbolAddress((void**)&p_v,     g_v);
    cudaGetSymbolAddress((void**)&p_out0,  g_out0);
    cudaGetSymbolAddress((void**)&p_outF,  g_outF);
    cudaGetSymbolAddress((void**)&p_rel,   g_rel);
    cudaGetSymbolAddress((void**)&p_time,  g_time);

    dim3 gatt(SS/AROWS, BB*HH);   // (32, 128) = 4096 blocks

    gather_kernel<<<TOK, EE>>>(item_emb, item_inputs, label_inputs, item_ids);

    // GEMM_A: x = relu(in2E @ lin_in_w + b)    [K=512, N=256]
    {
        GemmSegs s = {};
        s.W[0] = lin_in_w; s.bias[0] = lin_in_b; s.out[0] = p_x; s.epi[0] = 1;
        bf16gemm_seg<<<dim3(4, TOK/64), 128>>>(p_in2E, 2*EE, s);
    }
    // GEMM_B: query @ [Wc | Wg | Wq0 | Wq1]    [K=256, N=1024]
    {
        GemmSegs s = {};
        s.W[0] = Wc;        s.bias[0] = nullptr;  s.out[0] = p_cg; s.epi[0] = 2;
        s.W[1] = Wg;        s.bias[1] = nullptr;  s.out[1] = p_gg; s.epi[1] = 2;
        s.W[2] = Wq;        s.bias[2] = bq;       s.out[2] = p_q0; s.epi[2] = 0;
        s.W[3] = Wq+EE*EE;  s.bias[3] = bq+EE;    s.out[3] = p_q1; s.epi[3] = 0;
        bf16gemm_seg<<<dim3(16, TOK/64), 128>>>(p_query, EE, s);
    }
    rowsm_kernel<<<BB*SS, 256>>>(rel,       p_rel,  0);
    rowsm_kernel<<<BB*SS, 256>>>(timestamp, p_time, 1);

    // GEMM_C: x @ [Wk0 | Wv0]                  [K=256, N=512]
    {
        GemmSegs s = {};
        s.W[0] = Wk; s.bias[0] = bk; s.out[0] = p_k; s.epi[0] = 0;
        s.W[1] = Wv; s.bias[1] = bv; s.out[1] = p_v; s.epi[1] = 0;
        bf16gemm_seg<<<dim3(8, TOK/64), 128>>>(p_x, EE, s);
    }
    attn_tile_kernel<<<gatt, 256, ATT_SMEM>>>(p_q0, p_k, p_v, posK, posV, l1, l2,
                                              p_out0, nullptr, nullptr, 0);
    // GEMM_D: out0 @ [Wk1 | Wv1]               [K=256, N=512]
    {
        GemmSegs s = {};
        s.W[0] = Wk+EE*EE; s.bias[0] = bk+EE; s.out[0] = p_k; s.epi[0] = 0;
        s.W[1] = Wv+EE*EE; s.bias[1] = bv+EE; s.out[1] = p_v; s.epi[1] = 0;
        bf16gemm_seg<<<dim3(8, TOK/64), 128>>>(p_out0, EE, s);
    }
    attn_tile_kernel<<<gatt, 256, ATT_SMEM>>>(p_q1, p_k, p_v, posK, posV, l1, l2,
                                              p_outF, p_out0, attn_out, 1);

    logits_kernel<<<TOK/8, 256>>>(p_outF, lin_out_w, lin_out_b, out);
}

// round 16
// speedup vs baseline: 1.0783x; 1.0737x over previous
#include <cuda_runtime.h>
#include <cuda_bf16.h>
#include <math.h>
#include <stdint.h>

#define BB 16
#define SS 512
#define EE 256
#define HH 8
#define DD 32
#define TOK (BB*SS)
#define NEGBIG -1e30f

// ---------------- scratch ----------------
__device__ float g_in2E [TOK*2*EE];
__device__ float g_query[TOK*EE];
__device__ float g_x    [TOK*EE];
__device__ float g_cg   [TOK*EE];
__device__ float g_gg   [TOK*EE];
__device__ float g_q0   [TOK*EE];
__device__ float g_q1   [TOK*EE];
__device__ float g_k    [TOK*EE];
__device__ float g_v    [TOK*EE];
__device__ float g_out0 [TOK*EE];
__device__ float g_outF [TOK*EE];
__device__ float g_rel  [(size_t)BB*SS*SS];
__device__ float g_time [(size_t)BB*SS*SS];

// ---------------- fast exp on the FMA pipe ----------------
__device__ __forceinline__ float fexp(float x) {
    x = fmaxf(-80.0f, fminf(x, 80.0f));
    float y = x * 1.4426950408889634f;
    float t = y + 12582912.0f;               // rint via magic number
    int   e = __float_as_int(t) - 0x4B400000;
    float f = y - (t - 12582912.0f);         // [-0.5, 0.5]
    float p =            1.3333558146428443e-3f;
    p = fmaf(p, f, 9.6181298420717e-3f);
    p = fmaf(p, f, 5.550410866482158e-2f);
    p = fmaf(p, f, 2.402265069591007e-1f);
    p = fmaf(p, f, 6.931471805599453e-1f);
    p = fmaf(p, f, 1.0f);
    return p * __int_as_float((e + 127) << 23);
}

// ---------------- gather ----------------
__global__ void gather_kernel(const float* __restrict__ item_emb,
                              const int* __restrict__ item_inputs,
                              const int* __restrict__ label_inputs,
                              const int* __restrict__ item_ids)
{
    int tok = blockIdx.x;
    int t   = threadIdx.x;
    int idx = item_inputs[tok];
    int qid = item_ids[tok];
    float lab = (float)label_inputs[tok];
    float ie = item_emb[(size_t)idx*EE + t];
    g_in2E[(size_t)tok*2*EE + t]      = ie * lab;
    g_in2E[(size_t)tok*2*EE + EE + t] = ie * (1.0f - lab);
    g_query[(size_t)tok*EE + t] = item_emb[(size_t)qid*EE + t];
}

// ---------------- segmented bf16x3 tensor-core GEMM ----------------
struct GemmSegs {
    const float* W[4];
    const float* bias[4];
    float*       out[4];
    int          epi[4];
};

__device__ __forceinline__ uint32_t packbf(float v0, float v1) {
    __nv_bfloat16 a = __float2bfloat16_rn(v0);
    __nv_bfloat16 b = __float2bfloat16_rn(v1);
    return (uint32_t)__bfloat16_as_ushort(a) | ((uint32_t)__bfloat16_as_ushort(b) << 16);
}

#define MMA_BF16(d, a, b) \
    asm volatile("mma.sync.aligned.m16n8k16.row.col.f32.bf16.bf16.f32 " \
        "{%0,%1,%2,%3}, {%4,%5,%6,%7}, {%8,%9}, {%0,%1,%2,%3};\n" \
        : "+f"(d[0]), "+f"(d[1]), "+f"(d[2]), "+f"(d[3]) \
        : "r"(a.x), "r"(a.y), "r"(a.z), "r"(a.w), "r"(b.x), "r"(b.y))

__global__ __launch_bounds__(128)
void bf16gemm_seg(const float* __restrict__ A, int K, GemmSegs segs)
{
    __shared__ uint32_t As[2048];   // hi [0,1024), lo [1024,2048)
    __shared__ uint32_t Bs[2048];
    int t = threadIdx.x, lane = t & 31, wid = t >> 5;
    int wm = wid >> 1, wn = wid & 1;
    int m0 = blockIdx.y * 64, n0 = blockIdx.x * 64;
    int seg = n0 >> 8;
    const float* W    = segs.W[seg];
    const float* bias = segs.bias[seg];
    float*       Cout = segs.out[seg];
    int          epi  = segs.epi[seg];
    int ncol0 = n0 & 255;

    float acc[2][4][4];
    #pragma unroll
    for (int mi = 0; mi < 2; mi++)
        #pragma unroll
        for (int ni = 0; ni < 4; ni++)
            #pragma unroll
            for (int r = 0; r < 4; r++) acc[mi][ni][r] = 0.0f;

    for (int k0 = 0; k0 < K; k0 += 32) {
        __syncthreads();
        #pragma unroll
        for (int rep = 0; rep < 4; rep++) {
            int idx = t + rep*128;
            int row = idx >> 3;
            int kq  = (idx & 7) * 4;
            float4 av = *(const float4*)(A + (size_t)(m0+row)*K + k0 + kq);
            float v[4] = {av.x, av.y, av.z, av.w};
            int mt = row >> 4, mrow = row & 15;
            int g = mrow & 7, rh = mrow >> 3;
            #pragma unroll
            for (int pj = 0; pj < 2; pj++) {
                int k = kq + pj*2;
                int ks2 = k >> 4, kk = k & 15;
                int reg = rh + ((kk >> 3) << 1);
                int cq = (kk & 7) >> 1;
                float v0 = v[pj*2], v1 = v[pj*2+1];
                float h0 = __bfloat162float(__float2bfloat16_rn(v0));
                float h1 = __bfloat162float(__float2bfloat16_rn(v1));
                int addr = ((ks2*4 + mt)*32 + g*4 + cq)*4 + reg;
                As[addr]        = packbf(v0, v1);
                As[addr + 1024] = packbf(v0 - h0, v1 - h1);
            }
        }
        #pragma unroll
        for (int rep = 0; rep < 2; rep++) {
            int idx = t + rep*128;
            int kp = idx >> 4;
            int nq = (idx & 15) * 4;
            int k = kp*2;
            float4 b0 = *(const float4*)(W + (size_t)(k0+k  )*256 + ncol0 + nq);
            float4 b1 = *(const float4*)(W + (size_t)(k0+k+1)*256 + ncol0 + nq);
            float r0[4] = {b0.x, b0.y, b0.z, b0.w};
            float r1[4] = {b1.x, b1.y, b1.z, b1.w};
            int ks2 = k >> 4, kk = k & 15;
            int reg = kk >> 3, cq = (kk & 7) >> 1;
            #pragma unroll
            for (int j = 0; j < 4; j++) {
                int n = nq + j;
                int nt = n >> 3, g = n & 7;
                float h0 = __bfloat162float(__float2bfloat16_rn(r0[j]));
                float h1 = __bfloat162float(__float2bfloat16_rn(r1[j]));
                int addr = ((ks2*8 + nt)*32 + g*4 + cq)*2 + reg;
                Bs[addr]        = packbf(r0[j], r1[j]);
                Bs[addr + 1024] = packbf(r0[j] - h0, r1[j] - h1);
            }
        }
        __syncthreads();
        #pragma unroll
        for (int ks = 0; ks < 2; ks++) {
            uint4 ah[2], al[2];
            #pragma unroll
            for (int mi = 0; mi < 2; mi++) {
                ah[mi] = ((const uint4*)As)[(ks*4 + wm*2+mi)*32 + lane];
                al[mi] = ((const uint4*)As)[(ks*4 + wm*2+mi)*32 + lane + 256];
            }
            #pragma unroll
            for (int ni = 0; ni < 4; ni++) {
                uint2 bhp = ((const uint2*)Bs)[(ks*8 + wn*4+ni)*32 + lane];
                uint2 blp = ((const uint2*)Bs)[(ks*8 + wn*4+ni)*32 + lane + 512];
                #pragma unroll
                for (int mi = 0; mi < 2; mi++) {
                    MMA_BF16(acc[mi][ni], al[mi], bhp);
                    MMA_BF16(acc[mi][ni], ah[mi], blp);
                    MMA_BF16(acc[mi][ni], ah[mi], bhp);
                }
            }
        }
    }

    int g = lane >> 2, cq = lane & 3;
    #pragma unroll
    for (int mi = 0; mi < 2; mi++) {
        #pragma unroll
        for (int ni = 0; ni < 4; ni++) {
            #pragma unroll
            for (int r = 0; r < 4; r++) {
                int row = m0 + wm*32 + mi*16 + g + ((r >> 1) ? 8 : 0);
                int col = ncol0 + wn*32 + ni*8 + cq*2 + (r & 1);
                float v = acc[mi][ni][r];
                if (bias) v += bias[col];
                size_t oidx;
                if (epi == 0) {
                    int b = row >> 9, s = row & 511;
                    int h = col >> 5, d = col & 31;
                    oidx = (((size_t)(b*HH+h)*SS) + s)*DD + d;
                } else {
                    if (epi == 1) v = fmaxf(v, 0.0f);
                    else          v = 1.0f/(1.0f + fexp(-v));
                    oidx = (size_t)row*256 + col;
                }
                Cout[oidx] = v;
            }
        }
    }
}

// ---------------- row softmax: rel (mode0) / time (mode1) ----------------
__global__ void rowsm_kernel(const float* __restrict__ src, float* __restrict__ dst, int mode)
{
    int row = blockIdx.x;
    int i = row & (SS-1);
    int t = threadIdx.x;
    __shared__ float shs[8];
    const float2* sr = (const float2*)(src + (size_t)row*SS);
    float2 v = sr[t];
    int j0 = 2*t, j1 = 2*t + 1;
    float e0, e1;
    if (mode == 0) {
        e0 = (j0 <= i && v.x != 0.0f) ? fexp(v.x) : 0.0f;
        e1 = (j1 <= i && v.y != 0.0f) ? fexp(v.y) : 0.0f;
    } else {
        e0 = (j0 <= i) ? fexp(fexp(-fabsf(v.x))) : 0.0f;
        e1 = (j1 <= i) ? fexp(fexp(-fabsf(v.y))) : 0.0f;
    }
    int lane = t & 31, w = t >> 5;
    float s = e0 + e1;
    #pragma unroll
    for (int o = 16; o; o >>= 1) s += __shfl_xor_sync(0xffffffffu, s, o);
    if (lane == 0) shs[w] = s;
    __syncthreads();
    s = 0.0f;
    #pragma unroll
    for (int k = 0; k < 8; k++) s += shs[k];
    float inv = 1.0f / s;
    float2 o2 = make_float2(e0*inv, e1*inv);
    ((float2*)(dst + (size_t)row*SS))[t] = o2;
}

// ---------------- attention: 32 query rows / block, q in registers --------
#define ATT_SMEM ((32*512 + 32*32 + 2*2048 + 320 + 320)*4)
__global__ __launch_bounds__(256)
void attn_tile_kernel(const float* __restrict__ qh, const float* __restrict__ kh,
                      const float* __restrict__ vh,
                      const float* __restrict__ posK, const float* __restrict__ posV,
                      const float* __restrict__ l1p, const float* __restrict__ l2p,
                      float* __restrict__ out,
                      const float* __restrict__ out0_in,
                      float* __restrict__ attn_out,
                      int li)
{
    extern __shared__ float smf[];
    float* sc   = smf;                  // 32*512
    float* qs   = sc + 32*512;          // 32*32
    float* bufA = qs + 1024;            // 2048
    float* bufB = bufA + 2048;          // 2048
    float* qpk  = bufB + 2048;          // 320
    float* pvw  = qpk + 320;            // 320

    int it = blockIdx.x;
    int bh = blockIdx.y;
    int b = bh >> 3, h = bh & 7;
    int t = threadIdx.x;
    int i0 = it * 32;
    int jact = (it/2 + 1) * 64;
    int ntile = jact >> 6;
    float l1 = l1p[0], l2 = l2p[0];
    float ca = (1.f-l1)*(1.f-l2), cb = l1*(1.f-l2), cc = l2;
    const float* qbase = qh + (size_t)bh*SS*DD;
    const float* kbase = kh + (size_t)bh*SS*DD;
    const float* vbase = vh + (size_t)bh*SS*DD;

    ((float4*)qs)[t] = ((const float4*)(qbase + (size_t)i0*DD))[t];
    __syncthreads();
    for (int f = t; f < 320; f += 256) {
        int ii = f / 10, p = f % 10;
        float s = 0.f;
        #pragma unroll
        for (int d = 0; d < 32; d++) s += qs[ii*32+d] * posK[p*32+d];
        qpk[f] = s;
    }

    // ---- QK phase: q rows hoisted to registers, double-buffered k tiles ----
    {
        #pragma unroll
        for (int rep = 0; rep < 2; rep++) {
            int idx = t + rep*256;
            int jj = idx >> 3, dq = (idx & 7) * 4;
            float4 kv = *(const float4*)(kbase + (size_t)jj*DD + dq);
            bufA[(dq+0)*64 + jj] = kv.x;
            bufA[(dq+1)*64 + jj] = kv.y;
            bufA[(dq+2)*64 + jj] = kv.z;
            bufA[(dq+3)*64 + jj] = kv.w;
        }
        __syncthreads();
        int rg = t >> 4, cg = t & 15;
        int r0 = rg*2, r1 = r0 + 1;
        // hoist both q rows into registers (smem-limited occupancy -> regs free)
        float q0r[32], q1r[32];
        #pragma unroll
        for (int d = 0; d < 32; d += 4) {
            float4 a0 = *(const float4*)(qs + r0*32 + d);
            float4 a1 = *(const float4*)(qs + r1*32 + d);
            q0r[d+0]=a0.x; q0r[d+1]=a0.y; q0r[d+2]=a0.z; q0r[d+3]=a0.w;
            q1r[d+0]=a1.x; q1r[d+1]=a1.y; q1r[d+2]=a1.z; q1r[d+3]=a1.w;
        }
        const float scale = 0.17677669529663687f;   // 1/sqrt(32)
        for (int jt = 0; jt < ntile; jt++) {
            float* cur = (jt & 1) ? bufB : bufA;
            float* nxt = (jt & 1) ? bufA : bufB;
            float4 pre[2];
            int jjp[2], dqp[2];
            if (jt+1 < ntile) {
                int j0n = (jt+1)*64;
                #pragma unroll
                for (int rep = 0; rep < 2; rep++) {
                    int idx = t + rep*256;
                    jjp[rep] = idx >> 3; dqp[rep] = (idx & 7) * 4;
                    pre[rep] = *(const float4*)(kbase + (size_t)(j0n+jjp[rep])*DD + dqp[rep]);
                }
            }
            float ac[2][4] = {};
            #pragma unroll
            for (int d = 0; d < 32; d++) {
                float4 bv = *(const float4*)(cur + d*64 + cg*4);
                float a0 = q0r[d], a1 = q1r[d];
                ac[0][0] += a0*bv.x; ac[0][1] += a0*bv.y;
                ac[0][2] += a0*bv.z; ac[0][3] += a0*bv.w;
                ac[1][0] += a1*bv.x; ac[1][1] += a1*bv.y;
                ac[1][2] += a1*bv.z; ac[1][3] += a1*bv.w;
            }
            int j0 = jt*64;
            #pragma unroll
            for (int r = 0; r < 2; r++) {
                int ii = r0 + r, i = i0 + ii;
                float o4[4];
                #pragma unroll
                for (int n = 0; n < 4; n++) {
                    int j = j0 + cg*4 + n;
                    o4[n] = (j <= i) ? (ac[r][n] + qpk[ii*10 + min(i-j, 9)]) * scale
                                     : NEGBIG;
                }
                *(float4*)(sc + ii*512 + j0 + cg*4) = make_float4(o4[0],o4[1],o4[2],o4[3]);
            }
            if (jt+1 < ntile) {
                #pragma unroll
                for (int rep = 0; rep < 2; rep++) {
                    nxt[(dqp[rep]+0)*64 + jjp[rep]] = pre[rep].x;
                    nxt[(dqp[rep]+1)*64 + jjp[rep]] = pre[rep].y;
                    nxt[(dqp[rep]+2)*64 + jjp[rep]] = pre[rep].z;
                    nxt[(dqp[rep]+3)*64 + jjp[rep]] = pre[rep].w;
                }
            }
            __syncthreads();
        }
    }

    // ---- fused softmax + blend + buckets: warp w owns rows w*4..w*4+3 ----
    int w = t >> 5, lane = t & 31;
    int pairs = jact >> 1;
    for (int ii = w*4; ii < w*4 + 4; ii++) {
        int i = i0 + ii;
        float2* srow = (float2*)(sc + ii*512);
        float s = 0.f;
        for (int jp = lane; jp < pairs; jp += 32) {
            float2 e2 = srow[jp];
            e2.x = fexp(e2.x); e2.y = fexp(e2.y);
            srow[jp] = e2;
            s += e2.x + e2.y;
        }
        #pragma unroll
        for (int o = 16; o; o >>= 1) s += __shfl_xor_sync(0xffffffffu, s, o);
        float cap = ca / s;
        const float2* rel2 = (const float2*)(g_rel  + (size_t)(b*SS + i)*SS);
        const float2* tm2  = (const float2*)(g_time + (size_t)(b*SS + i)*SS);
        float unif = 1.0f / (float)(i + 1);
        float2* aout = attn_out ? (float2*)(attn_out + ((size_t)bh*SS + i)*SS) : nullptr;
        float s2 = 0.f;
        for (int jp = lane; jp < pairs; jp += 32) {
            float2 e2 = srow[jp];
            float2 r2 = rel2[jp];
            float tvx, tvy;
            if (li == 0) { float2 tt = tm2[jp]; tvx = tt.x; tvy = tt.y; }
            else {
                int j = jp*2;
                tvx = (j   <= i) ? unif : 0.0f;
                tvy = (j+1 <= i) ? unif : 0.0f;
            }
            float pfx = fmaf(cap, e2.x, fmaf(cb, r2.x, cc*tvx));
            float pfy = fmaf(cap, e2.y, fmaf(cb, r2.y, cc*tvy));
            float2 pf2 = make_float2(pfx, pfy);
            srow[jp] = pf2;
            if (aout) aout[jp] = pf2;
            s2 += pfx + pfy;
        }
        #pragma unroll
        for (int o = 16; o; o >>= 1) s2 += __shfl_xor_sync(0xffffffffu, s2, o);
        if (lane < 10) {
            int j = i - lane;
            pvw[ii*10 + lane] = (j >= 0) ? sc[ii*512 + j] : 0.0f;
        }
        __syncwarp();
        if (lane == 0) {
            float sum8 = 0.f;
            #pragma unroll
            for (int p = 0; p < 9; p++) sum8 += pvw[ii*10 + p];
            pvw[ii*10 + 9] = s2 - sum8;
        }
        __syncwarp();
    }
    if (attn_out) {
        int wtail = SS - jact;
        if (wtail > 0) {
            int cnt = (32 * wtail) >> 2;
            for (int f = t; f < cnt; f += 256) {
                int ii = (f*4) / wtail;
                int off = (f*4) % wtail;
                *(float4*)(attn_out + ((size_t)bh*SS + i0 + ii)*SS + jact + off) =
                    make_float4(0.f,0.f,0.f,0.f);
            }
        }
    }
    __syncthreads();

    // ---- PV phase: double-buffered v tiles ----
    {
        #pragma unroll
        for (int rep = 0; rep < 2; rep++)
            ((float4*)bufA)[t + rep*256] = ((const float4*)vbase)[t + rep*256];
        __syncthreads();
        int rg = t >> 3, cg = t & 7;
        float o0 = 0.f, o1 = 0.f, o2 = 0.f, o3 = 0.f;
        for (int jt = 0; jt < ntile; jt++) {
            float* cur = (jt & 1) ? bufB : bufA;
            float* nxt = (jt & 1) ? bufA : bufB;
            float4 pre[2];
            if (jt+1 < ntile) {
                #pragma unroll
                for (int rep = 0; rep < 2; rep++)
                    pre[rep] = ((const float4*)(vbase + (size_t)(jt+1)*64*DD))[t + rep*256];
            }
            const float* srow = sc + rg*512 + jt*64;
            #pragma unroll 4
            for (int jj = 0; jj < 64; jj++) {
                float p = srow[jj];
                float4 v4 = *(const float4*)(cur + jj*32 + cg*4);
                o0 += p*v4.x; o1 += p*v4.y; o2 += p*v4.z; o3 += p*v4.w;
            }
            if (jt+1 < ntile) {
                #pragma unroll
                for (int rep = 0; rep < 2; rep++)
                    ((float4*)nxt)[t + rep*256] = pre[rep];
            }
            __syncthreads();
        }
        #pragma unroll
        for (int p = 0; p < 10; p++) {
            float wv = pvw[rg*10 + p];
            float4 pv4 = *(const float4*)(posV + p*32 + cg*4);
            o0 += wv*pv4.x; o1 += wv*pv4.y; o2 += wv*pv4.z; o3 += wv*pv4.w;
        }
        int tok = b*SS + i0 + rg;
        int e0 = h*DD + cg*4;
        float4 gg4 = *(const float4*)(g_gg + (size_t)tok*EE + e0);
        float4 cg4 = *(const float4*)(g_cg + (size_t)tok*EE + e0);
        float4 val;
        val.x = gg4.x + (1.0f - cg4.x)*o0;
        val.y = gg4.y + (1.0f - cg4.y)*o1;
        val.z = gg4.z + (1.0f - cg4.z)*o2;
        val.w = gg4.w + (1.0f - cg4.w)*o3;
        if (li == 0) {
            *(float4*)(out + (size_t)tok*EE + e0) = val;
        } else {
            float4 b4 = *(const float4*)(out0_in + (size_t)tok*EE + e0);
            val.x = b4.x + fmaxf(val.x, 0.f);
            val.y = b4.y + fmaxf(val.y, 0.f);
            val.z = b4.z + fmaxf(val.z, 0.f);
            val.w = b4.w + fmaxf(val.w, 0.f);
            *(float4*)(out + (size_t)tok*EE + e0) = val;
        }
    }
}

// ---------------- final logits ----------------
__global__ void logits_kernel(const float* __restrict__ x, const float* __restrict__ wv,
                              const float* __restrict__ bv, float* __restrict__ out)
{
    int w = threadIdx.x >> 5, lane = threadIdx.x & 31;
    int tok = blockIdx.x*8 + w;
    float s = 0.f;
    for (int j = lane; j < EE; j += 32) s += x[(size_t)tok*EE + j] * wv[j];
    #pragma unroll
    for (int o = 16; o; o >>= 1) s += __shfl_xor_sync(0xffffffffu, s, o);
    if (lane == 0) out[tok] = s + bv[0];
}

extern "C" void kernel_launch(void* const* d_in, const int* in_sizes, int n_in,
                              void* d_out, int out_size)
{
    const int*   item_inputs  = (const int*)  d_in[2];
    const int*   label_inputs = (const int*)  d_in[3];
    const int*   item_ids     = (const int*)  d_in[4];
    const float* rel          = (const float*)d_in[5];
    const float* timestamp    = (const float*)d_in[6];
    const float* item_emb     = (const float*)d_in[7];
    const float* posK         = (const float*)d_in[8];
    const float* posV         = (const float*)d_in[9];
    const float* Wc           = (const float*)d_in[10];
    const float* Wg           = (const float*)d_in[11];
    const float* lin_in_w     = (const float*)d_in[12];
    const float* lin_in_b     = (const float*)d_in[13];
    const float* Wq           = (const float*)d_in[14];
    const float* bq           = (const float*)d_in[15];
    const float* Wk           = (const float*)d_in[16];
    const float* bk           = (const float*)d_in[17];
    const float* Wv           = (const float*)d_in[18];
    const float* bv           = (const float*)d_in[19];
    const float* l1           = (const float*)d_in[20];
    const float* l2           = (const float*)d_in[21];
    const float* lin_out_w    = (const float*)d_in[22];
    const float* lin_out_b    = (const float*)d_in[23];
    float* out = (float*)d_out;
    float* attn_out = out + TOK;   // [16,8,512,512] after [16,512,1]

    static int attr_done = 0;
    if (!attr_done) {
        cudaFuncSetAttribute(attn_tile_kernel,
                             cudaFuncAttributeMaxDynamicSharedMemorySize, ATT_SMEM);
        attr_done = 1;
    }

    float *p_in2E, *p_query, *p_x, *p_cg, *p_gg;
    float *p_q0, *p_q1, *p_k, *p_v, *p_out0, *p_outF, *p_rel, *p_time;
    cudaGetSymbolAddress((void**)&p_in2E,  g_in2E);
    cudaGetSymbolAddress((void**)&p_query, g_query);
    cudaGetSymbolAddress((void**)&p_x,     g_x);
    cudaGetSymbolAddress((void**)&p_cg,    g_cg);
    cudaGetSymbolAddress((void**)&p_gg,    g_gg);
    cudaGetSymbolAddress((void**)&p_q0,    g_q0);
    cudaGetSymbolAddress((void**)&p_q1,    g_q1);
    cudaGetSymbolAddress((void**)&p_k,     g_k);
    cudaGetSymbolAddress((void**)&p_v,     g_v);
    cudaGetSymbolAddress((void**)&p_out0,  g_out0);
    cudaGetSymbolAddress((void**)&p_outF,  g_outF);
    cudaGetSymbolAddress((void**)&p_rel,   g_rel);
    cudaGetSymbolAddress((void**)&p_time,  g_time);

    dim3 gatt(16, BB*HH);   // (16, 128) = 2048 blocks, 32 rows each

    gather_kernel<<<TOK, EE>>>(item_emb, item_inputs, label_inputs, item_ids);

    // GEMM_A: x = relu(in2E @ lin_in_w + b)    [K=512, N=256]
    {
        GemmSegs s = {};
        s.W[0] = lin_in_w; s.bias[0] = lin_in_b; s.out[0] = p_x; s.epi[0] = 1;
        bf16gemm_seg<<<dim3(4, TOK/64), 128>>>(p_in2E, 2*EE, s);
    }
    // GEMM_B: query @ [Wc | Wg | Wq0 | Wq1]    [K=256, N=1024]
    {
        GemmSegs s = {};
        s.W[0] = Wc;        s.bias[0] = nullptr;  s.out[0] = p_cg; s.epi[0] = 2;
        s.W[1] = Wg;        s.bias[1] = nullptr;  s.out[1] = p_gg; s.epi[1] = 2;
        s.W[2] = Wq;        s.bias[2] = bq;       s.out[2] = p_q0; s.epi[2] = 0;
        s.W[3] = Wq+EE*EE;  s.bias[3] = bq+EE;    s.out[3] = p_q1; s.epi[3] = 0;
        bf16gemm_seg<<<dim3(16, TOK/64), 128>>>(p_query, EE, s);
    }
    rowsm_kernel<<<BB*SS, 256>>>(rel,       p_rel,  0);
    rowsm_kernel<<<BB*SS, 256>>>(timestamp, p_time, 1);

    // GEMM_C: x @ [Wk0 | Wv0]                  [K=256, N=512]
    {
        GemmSegs s = {};
        s.W[0] = Wk; s.bias[0] = bk; s.out[0] = p_k; s.epi[0] = 0;
        s.W[1] = Wv; s.bias[1] = bv; s.out[1] = p_v; s.epi[1] = 0;
        bf16gemm_seg<<<dim3(8, TOK/64), 128>>>(p_x, EE, s);
    }
    attn_tile_kernel<<<gatt, 256, ATT_SMEM>>>(p_q0, p_k, p_v, posK, posV, l1, l2,
                                              p_out0, nullptr, nullptr, 0);
    // GEMM_D: out0 @ [Wk1 | Wv1]               [K=256, N=512]
    {
        GemmSegs s = {};
        s.W[0] = Wk+EE*EE; s.bias[0] = bk+EE; s.out[0] = p_k; s.epi[0] = 0;
        s.W[1] = Wv+EE*EE; s.bias[1] = bv+EE; s.out[1] = p_v; s.epi[1] = 0;
        bf16gemm_seg<<<dim3(8, TOK/64), 128>>>(p_out0, EE, s);
    }
    attn_tile_kernel<<<gatt, 256, ATT_SMEM>>>(p_q1, p_k, p_v, posK, posV, l1, l2,
                                              p_outF, p_out0, attn_out, 1);

    logits_kernel<<<TOK/8, 256>>>(p_outF, lin_out_w, lin_out_b, out);
}